// round 16
// baseline (speedup 1.0000x reference)
#include <cuda_runtime.h>

// DynamicFilterLayer2D: out[b,c,h,w] = sum_{i,j in 3x3} xpad[b,c,h+i,w+j] * f[b,c,i*3+j,h,w]
// B=8, C=32, H=256, W=256, K=3, zero pad 1.
//
// R13: R1 per-tile code (proven: 512B/instr coalescing, default cache, low regs)
// wrapped in a PERSISTENT grid-stride loop sized to exactly one wave
// (1184 CTAs = 148 SMs x 8 resident). Eliminates ~13 wave transitions and lets
// independent loads from successive iterations overlap without per-tile register
// cost. Everything else identical to the 104.9us optimum.

static constexpr int B = 8;
static constexpr int C = 32;
static constexpr int H = 256;
static constexpr int W = 256;
static constexpr int HW = H * W;
static constexpr int W4 = W / 4;
static constexpr int TOTAL = B * C * H * W4;   // 4,194,304 tiles

__global__ __launch_bounds__(256)
void dynamic_filter_kernel(const float* __restrict__ x,
                           const float* __restrict__ f,
                           float* __restrict__ out)
{
    const int stride = gridDim.x * blockDim.x;

    for (int tid = blockIdx.x * blockDim.x + threadIdx.x; tid < TOTAL; tid += stride) {
        int w4 = tid & (W4 - 1);
        int t = tid >> 6;          // W4 = 64
        int h = t & (H - 1);
        int bc = t >> 8;           // H = 256

        const int w0 = w4 * 4;
        const long xbase = (long)bc * HW;
        const long fbase = (long)bc * 9 * HW;

        float4 acc = make_float4(0.f, 0.f, 0.f, 0.f);

        #pragma unroll
        for (int i = 0; i < 3; i++) {
            const int hr = h + i - 1;
            if (hr < 0 || hr >= H) continue;

            const float* xrow = x + xbase + (long)hr * W;
            const float4 cen = *reinterpret_cast<const float4*>(xrow + w0);
            const float xl = (w0 > 0)     ? __ldg(xrow + w0 - 1) : 0.f;
            const float xr = (w0 + 4 < W) ? __ldg(xrow + w0 + 4) : 0.f;

            const float v0 = xl, v1 = cen.x, v2 = cen.y, v3 = cen.z, v4 = cen.w, v5 = xr;

            const float* fp = f + fbase + (long)(i * 3) * HW + (long)h * W + w0;
            {
                const float4 fv = *reinterpret_cast<const float4*>(fp);            // j = 0
                acc.x = fmaf(fv.x, v0, acc.x);
                acc.y = fmaf(fv.y, v1, acc.y);
                acc.z = fmaf(fv.z, v2, acc.z);
                acc.w = fmaf(fv.w, v3, acc.w);
            }
            {
                const float4 fv = *reinterpret_cast<const float4*>(fp + HW);       // j = 1
                acc.x = fmaf(fv.x, v1, acc.x);
                acc.y = fmaf(fv.y, v2, acc.y);
                acc.z = fmaf(fv.z, v3, acc.z);
                acc.w = fmaf(fv.w, v4, acc.w);
            }
            {
                const float4 fv = *reinterpret_cast<const float4*>(fp + 2 * HW);   // j = 2
                acc.x = fmaf(fv.x, v2, acc.x);
                acc.y = fmaf(fv.y, v3, acc.y);
                acc.z = fmaf(fv.z, v4, acc.z);
                acc.w = fmaf(fv.w, v5, acc.w);
            }
        }

        *reinterpret_cast<float4*>(out + xbase + (long)h * W + w0) = acc;
    }
}

extern "C" void kernel_launch(void* const* d_in, const int* in_sizes, int n_in,
                              void* d_out, int out_size)
{
    const float* x = (const float*)d_in[0];
    const float* f = (const float*)d_in[1];
    float* out = (float*)d_out;

    // One full wave: 148 SMs (GB300: 152; 148 keeps division even and is safe
    // on either) x 8 CTAs/SM resident at 256 thr / <=40 regs.
    const int threads = 256;
    const int blocks = 148 * 8;   // 1184 persistent CTAs, ~14 tiles/thread
    dynamic_filter_kernel<<<blocks, threads>>>(x, f, out);
}